// round 12
// baseline (speedup 1.0000x reference)
#include <cuda_runtime.h>
#include <cuda_fp16.h>
#include <cstdint>

// ============================================================================
// out[8192,2048] = x[8192,2048] @ W[2048,2048]^T + b   (fp32 in/out)
//
// fp16 mma.sync.m16n8k16, fp32 accum (tcgen05.ld rejected by plain sm_103
// ptxas). rel_err 2.06e-4 vs 1e-3 threshold.
//
// R12 vs R11 (170.1us = GEMM 148.8 @ tensor 75.7%, alu 15.1%):
//  - mainloop unrolled by ring period (3): stage indices, mbarrier
//    addresses, STAGE offsets all compile-time; per-stage parity in
//    dedicated registers toggled by ^=1. Deletes the dynamic ring state
//    machine (s wrap, parity bitmask shifts) from the hot path.
//  - Semantics identical to R11 (same wait/arrive order, same produce
//    slot (s+2)%3, same pre-tripped empty[2]); remainder bodies cover
//    iters=32 (10x3+2) and iters=16 (5x3+1) exactly.
//  - Early empty-arrive, tail split-K, protocol, tiles, prep: FROZEN.
// ============================================================================

#define DIM      2048
#define M_TOTAL  8192
#define BM       128
#define BN       128
#define BK       64
#define THREADS  256
#define STAGES   3
#define KITERS   (DIM / BK)          // 32

#define NTILE_X  (DIM / BN)          // 16
#define NTILES   ((M_TOTAL / BM) * NTILE_X)   // 1024
#define FULL_TILES 888
#define TAIL_TILES (NTILES - FULL_TILES)      // 136
#define GRID_TOTAL (FULL_TILES + 2 * TAIL_TILES)  // 1160

__device__ __half g_Xh[(size_t)M_TOTAL * DIM];   // 32 MB
__device__ __half g_Wh[(size_t)DIM * DIM];       //  8 MB

#define A_BYTES     16384
#define STAGE_BYTES 32768
#define TILES_BYTES (STAGES * STAGE_BYTES)       // 98304
#define SMEM_BYTES  (TILES_BYTES + 64)

// ---------------------------------------------------------------------------
__device__ __forceinline__ uint32_t smem_u32(const void* p) {
    uint32_t a;
    asm("{ .reg .u64 t; cvta.to.shared.u64 t, %1; cvt.u32.u64 %0, t; }"
        : "=r"(a) : "l"(p));
    return a;
}
__device__ __forceinline__ uint32_t swz(uint32_t b) {   // SW128
    return b ^ ((b >> 3) & 0x70);
}
__device__ __forceinline__ void cp16(uint32_t dst, const void* src) {
    asm volatile("cp.async.cg.shared.global [%0], [%1], 16;"
                 :: "r"(dst), "l"(src));
}
__device__ __forceinline__ void cp_arrive(uint32_t mbar) {
    asm volatile("cp.async.mbarrier.arrive.noinc.shared::cta.b64 [%0];"
                 :: "r"(mbar) : "memory");
}
__device__ __forceinline__ void mbar_init(uint32_t mbar, uint32_t cnt) {
    asm volatile("mbarrier.init.shared.b64 [%0], %1;" :: "r"(mbar), "r"(cnt) : "memory");
}
__device__ __forceinline__ void mbar_arrive(uint32_t mbar) {
    asm volatile("mbarrier.arrive.shared::cta.b64 _, [%0];" :: "r"(mbar) : "memory");
}
__device__ __forceinline__ void mbar_wait(uint32_t mbar, uint32_t parity) {
    asm volatile(
        "{\n\t.reg .pred P;\n\t"
        "WAITLP_%=:\n\t"
        "mbarrier.try_wait.parity.acquire.cta.shared::cta.b64 P, [%0], %1, 0x989680;\n\t"
        "@!P bra WAITLP_%=;\n\t}"
        :: "r"(mbar), "r"(parity) : "memory");
}
__device__ __forceinline__ void redf(float* p, float v) {
    asm volatile("red.global.add.f32 [%0], %1;" :: "l"(p), "f"(v) : "memory");
}

#define LDSM4(r0, r1, r2, r3, addr) \
    asm volatile("ldmatrix.sync.aligned.m8n8.x4.shared.b16 {%0,%1,%2,%3}, [%4];" \
                 : "=r"(r0), "=r"(r1), "=r"(r2), "=r"(r3) : "r"(addr))

#define MMA16816(c0, c1, c2, c3, a0, a1, a2, a3, b0, b1) \
    asm volatile("mma.sync.aligned.m16n8k16.row.col.f32.f16.f16.f32 " \
                 "{%0,%1,%2,%3}, {%4,%5,%6,%7}, {%8,%9}, {%0,%1,%2,%3};" \
                 : "+f"(c0), "+f"(c1), "+f"(c2), "+f"(c3) \
                 : "r"(a0), "r"(a1), "r"(a2), "r"(a3), "r"(b0), "r"(b1))

// ============================================================================
// prep: fp32 -> fp16 convert (8 floats/thread) + bias-init of tail tiles
// ============================================================================
#define NX8 ((M_TOTAL * DIM) / 8)    // 2,097,152
#define NW8 ((DIM * DIM) / 8)        //   524,288
#define NT4 (TAIL_TILES * (BM * BN) / 4)     // 557,056
#define PREP_BLOCKS ((NX8 + NW8 + NT4) / 256)

__device__ __forceinline__ uint4 pack8(float4 v0, float4 v1) {
    __half2 h0 = __floats2half2_rn(v0.x, v0.y);
    __half2 h1 = __floats2half2_rn(v0.z, v0.w);
    __half2 h2 = __floats2half2_rn(v1.x, v1.y);
    __half2 h3 = __floats2half2_rn(v1.z, v1.w);
    uint4 p;
    p.x = *reinterpret_cast<uint32_t*>(&h0);
    p.y = *reinterpret_cast<uint32_t*>(&h1);
    p.z = *reinterpret_cast<uint32_t*>(&h2);
    p.w = *reinterpret_cast<uint32_t*>(&h3);
    return p;
}

__global__ void __launch_bounds__(256) prep_kernel(const float4* __restrict__ x,
                                                   const float4* __restrict__ W,
                                                   const float4* __restrict__ bias4,
                                                   float4* __restrict__ out4) {
    int i = blockIdx.x * 256 + threadIdx.x;
    if (i < NX8 + NW8) {
        const float4* src;
        uint4* dst;
        int j;
        if (i < NX8) { src = x; dst = reinterpret_cast<uint4*>(g_Xh); j = i; }
        else         { src = W; dst = reinterpret_cast<uint4*>(g_Wh); j = i - NX8; }
        float4 v0 = src[2 * j];
        float4 v1 = src[2 * j + 1];
        dst[j] = pack8(v0, v1);
    } else {
        int j = i - (NX8 + NW8);
        int tile = FULL_TILES + (j >> 12);
        int e = j & 4095;
        int r  = e >> 5;
        int c4 = e & 31;
        int m_tile = tile >> 4;
        int n_tile = tile & 15;
        int bidx = n_tile * 32 + c4;
        out4[(size_t)(m_tile * BM + r) * (DIM / 4) + bidx] = __ldg(&bias4[bidx]);
    }
}

// ============================================================================
// GEMM: 128x128 CTA tile, 8 warps (2Mx4N), warp tile 64x32, 3-stage mbarrier
// pipeline (compile-time stages), early empty-arrive, 2 CTAs/SM.
// ============================================================================
struct Frag { uint32_t a[4][4]; uint32_t b[2][4]; };

__device__ __forceinline__ void ldsm_frags(Frag& f, uint32_t aB, uint32_t bB,
                                           uint32_t a_base, uint32_t b_base, int k16) {
    const uint32_t kb = (uint32_t)(k16 * 32);
    #pragma unroll
    for (int mt = 0; mt < 4; mt++) {
        uint32_t off = swz(a_base + kb) + (uint32_t)(mt << 11);
        LDSM4(f.a[mt][0], f.a[mt][1], f.a[mt][2], f.a[mt][3], aB + off);
    }
    #pragma unroll
    for (int p = 0; p < 2; p++) {
        uint32_t off = swz(b_base + kb) + (uint32_t)(p << 11);
        LDSM4(f.b[p][0], f.b[p][1], f.b[p][2], f.b[p][3], bB + off);
    }
}

__device__ __forceinline__ void mma_frags(float c[4][4][4], const Frag& f) {
    #pragma unroll
    for (int mt = 0; mt < 4; mt++)
        #pragma unroll
        for (int nb = 0; nb < 4; nb++)
            MMA16816(c[mt][nb][0], c[mt][nb][1], c[mt][nb][2], c[mt][nb][3],
                     f.a[mt][0], f.a[mt][1], f.a[mt][2], f.a[mt][3],
                     f.b[nb >> 1][(nb & 1) * 2], f.b[nb >> 1][(nb & 1) * 2 + 1]);
}

// One pipeline body with compile-time stage S (consume) and SW=(S+2)%3
// (produce target). PF/PE are dedicated parity registers for those stages.
// Ordering identical to the proven R11 loop body.
#define PIPE_BODY(S, SW, PF, PE, IT) do {                                      \
    mbar_wait(fullb + (S) * 8, PF); PF ^= 1u;                                  \
    const uint32_t aB = sbase + (uint32_t)((S) * STAGE_BYTES);                 \
    const uint32_t bB = aB + A_BYTES;                                          \
    ldsm_frags(f0, aB, bB, a_base, b_base, 0);                                 \
    ldsm_frags(f1, aB, bB, a_base, b_base, 1);                                 \
    mma_frags(c, f0);                                                          \
    if ((IT) + 2 < iters) {                                                    \
        mbar_wait(emptyb + (SW) * 8, PE); PE ^= 1u;                            \
        const uint32_t st = sbase + (uint32_t)((SW) * STAGE_BYTES);            \
        const int kc = ((IT) + 2) * BK;                                        \
        _Pragma("unroll")                                                      \
        for (int i = 0; i < 4; i++)                                            \
            cp16(st + dOff + (uint32_t)(i << 12),                              \
                 aSrc + (size_t)(i * 32) * DIM + kc);                          \
        _Pragma("unroll")                                                      \
        for (int i = 0; i < 4; i++)                                            \
            cp16(st + A_BYTES + dOff + (uint32_t)(i << 12),                    \
                 bSrc + (size_t)(i * 32) * DIM + kc);                          \
        cp_arrive(fullb + (SW) * 8);                                           \
    }                                                                          \
    ldsm_frags(f0, aB, bB, a_base, b_base, 2);                                 \
    mma_frags(c, f1);                                                          \
    ldsm_frags(f1, aB, bB, a_base, b_base, 3);                                 \
    if (lane == 0) mbar_arrive(emptyb + (S) * 8);                              \
    mma_frags(c, f0);                                                          \
    mma_frags(c, f1);                                                          \
} while (0)

__global__ void __launch_bounds__(THREADS, 2) gemm_fp16_kernel(
    float* __restrict__ out, const float* __restrict__ bias)
{
    extern __shared__ __align__(1024) char smem[];
    const uint32_t sbase = smem_u32(smem);
    const int tid  = threadIdx.x;
    const int lane = tid & 31;
    const int wid  = tid >> 5;
    const int warp_m = wid & 1;
    const int warp_n = wid >> 1;
    const int bid  = blockIdx.x;

    // tile / K-range assignment (tail split-K)
    int tile, kBase, iters;
    bool splitk;
    if (bid < FULL_TILES) {
        tile = bid;  kBase = 0;  iters = KITERS;  splitk = false;
    } else {
        int idx = bid - FULL_TILES;
        tile = FULL_TILES + (idx >> 1);
        kBase = (idx & 1) * (DIM / 2);
        iters = KITERS / 2;
        splitk = true;
    }
    const int mBase = (tile >> 4) * BM;
    const int nBase = (tile & 15) * BN;

    const uint32_t fullb  = sbase + TILES_BYTES;
    const uint32_t emptyb = sbase + TILES_BYTES + 24;

    if (tid == 0) {
        #pragma unroll
        for (int s = 0; s < STAGES; s++) {
            mbar_init(fullb  + s * 8, THREADS);
            mbar_init(emptyb + s * 8, 8);
        }
        #pragma unroll
        for (int k = 0; k < 8; k++) mbar_arrive(emptyb + 2 * 8);
    }

    const int n0 = nBase + warp_n * 32 + (lane & 3) * 2;
    float2 bb[4];
    #pragma unroll
    for (int nb = 0; nb < 4; nb++)
        bb[nb] = __ldg(reinterpret_cast<const float2*>(bias + n0 + nb * 8));

    const int ldr = tid >> 3;
    const int ldc = (tid & 7) * 8;
    const __half* aSrc = g_Xh + (size_t)(mBase + ldr) * DIM + kBase + ldc;
    const __half* bSrc = g_Wh + (size_t)(nBase + ldr) * DIM + kBase + ldc;
    const uint32_t dOff = swz((uint32_t)(ldr * 128 + ldc * 2));

    float c[4][4][4];
    #pragma unroll
    for (int mt = 0; mt < 4; mt++)
        #pragma unroll
        for (int nb = 0; nb < 4; nb++)
            #pragma unroll
            for (int r = 0; r < 4; r++) c[mt][nb][r] = 0.0f;

    __syncthreads();

    // prologue: produce chunks 0,1 into buffers 0,1
    #pragma unroll
    for (int s = 0; s < 2; s++) {
        const uint32_t st = sbase + (uint32_t)s * STAGE_BYTES;
        #pragma unroll
        for (int i = 0; i < 4; i++)
            cp16(st + dOff + (uint32_t)(i << 12), aSrc + (size_t)(i * 32) * DIM + s * BK);
        #pragma unroll
        for (int i = 0; i < 4; i++)
            cp16(st + A_BYTES + dOff + (uint32_t)(i << 12), bSrc + (size_t)(i * 32) * DIM + s * BK);
        cp_arrive(fullb + s * 8);
    }

    const uint32_t a_base = (uint32_t)(((warp_m * 64 + (lane & 15)) << 7) + ((lane >> 4) << 4));
    const uint32_t b_base = (uint32_t)(((warp_n * 32 + ((lane >> 4) << 3) + (lane & 7)) << 7)
                                       + (((lane >> 3) & 1) << 4));

    // per-stage parity registers (compile-time stage binding)
    uint32_t pf0 = 0, pf1 = 0, pf2 = 0;
    uint32_t pe0 = 0, pe1 = 0, pe2 = 0;
    Frag f0, f1;

    // mainloop: unrolled by ring period 3. iters=32 -> 10x3 + bodies(0),(1);
    // iters=16 -> 5x3 + body(0). Stage sequence matches R11 exactly.
    int it = 0;
    for (; it + 3 <= iters; it += 3) {
        PIPE_BODY(0, 2, pf0, pe2, it);
        PIPE_BODY(1, 0, pf1, pe0, it + 1);
        PIPE_BODY(2, 1, pf2, pe1, it + 2);
    }
    if (it < iters) { PIPE_BODY(0, 2, pf0, pe2, it); it++; }
    if (it < iters) { PIPE_BODY(1, 0, pf1, pe0, it); }

    // epilogue
    const int m0 = mBase + warp_m * 64 + (lane >> 2);
    if (!splitk) {
        #pragma unroll
        for (int mt = 0; mt < 4; mt++) {
            #pragma unroll
            for (int nb = 0; nb < 4; nb++) {
                const int row = m0 + mt * 16;
                const int col = n0 + nb * 8;
                float2 v0, v1;
                v0.x = c[mt][nb][0] + bb[nb].x;  v0.y = c[mt][nb][1] + bb[nb].y;
                v1.x = c[mt][nb][2] + bb[nb].x;  v1.y = c[mt][nb][3] + bb[nb].y;
                *reinterpret_cast<float2*>(out + (size_t)row * DIM + col) = v0;
                *reinterpret_cast<float2*>(out + (size_t)(row + 8) * DIM + col) = v1;
            }
        }
    } else {
        #pragma unroll
        for (int mt = 0; mt < 4; mt++) {
            #pragma unroll
            for (int nb = 0; nb < 4; nb++) {
                const int row = m0 + mt * 16;
                const int col = n0 + nb * 8;
                float* p0 = out + (size_t)row * DIM + col;
                float* p1 = out + (size_t)(row + 8) * DIM + col;
                redf(p0,     c[mt][nb][0]);
                redf(p0 + 1, c[mt][nb][1]);
                redf(p1,     c[mt][nb][2]);
                redf(p1 + 1, c[mt][nb][3]);
            }
        }
    }
}

// ============================================================================
// kernel_launch — graph-capturable, allocation-free
// ============================================================================
extern "C" void kernel_launch(void* const* d_in, const int* in_sizes, int n_in,
                              void* d_out, int out_size) {
    const float* x = (const float*)d_in[0];
    const float* W = (const float*)d_in[1];
    const float* b = (const float*)d_in[2];
    float* out = (float*)d_out;
    (void)in_sizes; (void)n_in; (void)out_size;

    prep_kernel<<<PREP_BLOCKS, 256>>>((const float4*)x, (const float4*)W,
                                      (const float4*)b, (float4*)out);

    cudaFuncSetAttribute(gemm_fp16_kernel,
                         cudaFuncAttributeMaxDynamicSharedMemorySize, SMEM_BYTES);
    gemm_fp16_kernel<<<GRID_TOTAL, THREADS, SMEM_BYTES>>>(out, b);
}

// round 13
// speedup vs baseline: 1.4758x; 1.4758x over previous
#include <cuda_runtime.h>
#include <cuda_fp16.h>
#include <cstdint>

// ============================================================================
// out[8192,2048] = x[8192,2048] @ W[2048,2048]^T + b   (fp32 in/out)
//
// fp16 mma.sync.m16n8k16, fp32 accum (tcgen05.ld rejected by plain sm_103
// ptxas). rel_err 2.06e-4 vs 1e-3 threshold.
//
// R13 = R11 restored verbatim (best: 170.1us, GEMM 148.8 @ tensor 75.7%)
//       + streaming loads (__ldcs) in prep.
//  R12 post-mortem: unroll-by-3 grew the mainloop past the ~6KB L0 I$
//  (2 CTAs at different phases thrash it) -> +83us. The rolled R11 loop
//  (~1.7KB) is the local optimum; mainloop is FROZEN for good.
//  Prep loads are single-use -> evict-first policy preserves L2 for the
//  fp16 scratch the GEMM re-reads.
// ============================================================================

#define DIM      2048
#define M_TOTAL  8192
#define BM       128
#define BN       128
#define BK       64
#define THREADS  256
#define STAGES   3
#define KITERS   (DIM / BK)          // 32

#define NTILE_X  (DIM / BN)          // 16
#define NTILES   ((M_TOTAL / BM) * NTILE_X)   // 1024
#define FULL_TILES 888
#define TAIL_TILES (NTILES - FULL_TILES)      // 136
#define GRID_TOTAL (FULL_TILES + 2 * TAIL_TILES)  // 1160

__device__ __half g_Xh[(size_t)M_TOTAL * DIM];   // 32 MB
__device__ __half g_Wh[(size_t)DIM * DIM];       //  8 MB

#define A_BYTES     16384
#define STAGE_BYTES 32768
#define TILES_BYTES (STAGES * STAGE_BYTES)       // 98304
#define SMEM_BYTES  (TILES_BYTES + 64)

// ---------------------------------------------------------------------------
__device__ __forceinline__ uint32_t smem_u32(const void* p) {
    uint32_t a;
    asm("{ .reg .u64 t; cvta.to.shared.u64 t, %1; cvt.u32.u64 %0, t; }"
        : "=r"(a) : "l"(p));
    return a;
}
__device__ __forceinline__ uint32_t swz(uint32_t b) {   // SW128
    return b ^ ((b >> 3) & 0x70);
}
__device__ __forceinline__ void cp16(uint32_t dst, const void* src) {
    asm volatile("cp.async.cg.shared.global [%0], [%1], 16;"
                 :: "r"(dst), "l"(src));
}
__device__ __forceinline__ void cp_arrive(uint32_t mbar) {
    asm volatile("cp.async.mbarrier.arrive.noinc.shared::cta.b64 [%0];"
                 :: "r"(mbar) : "memory");
}
__device__ __forceinline__ void mbar_init(uint32_t mbar, uint32_t cnt) {
    asm volatile("mbarrier.init.shared.b64 [%0], %1;" :: "r"(mbar), "r"(cnt) : "memory");
}
__device__ __forceinline__ void mbar_arrive(uint32_t mbar) {
    asm volatile("mbarrier.arrive.shared::cta.b64 _, [%0];" :: "r"(mbar) : "memory");
}
__device__ __forceinline__ void mbar_wait(uint32_t mbar, uint32_t parity) {
    asm volatile(
        "{\n\t.reg .pred P;\n\t"
        "WAITLP_%=:\n\t"
        "mbarrier.try_wait.parity.acquire.cta.shared::cta.b64 P, [%0], %1, 0x989680;\n\t"
        "@!P bra WAITLP_%=;\n\t}"
        :: "r"(mbar), "r"(parity) : "memory");
}
__device__ __forceinline__ void redf(float* p, float v) {
    asm volatile("red.global.add.f32 [%0], %1;" :: "l"(p), "f"(v) : "memory");
}

#define LDSM4(r0, r1, r2, r3, addr) \
    asm volatile("ldmatrix.sync.aligned.m8n8.x4.shared.b16 {%0,%1,%2,%3}, [%4];" \
                 : "=r"(r0), "=r"(r1), "=r"(r2), "=r"(r3) : "r"(addr))

#define MMA16816(c0, c1, c2, c3, a0, a1, a2, a3, b0, b1) \
    asm volatile("mma.sync.aligned.m16n8k16.row.col.f32.f16.f16.f32 " \
                 "{%0,%1,%2,%3}, {%4,%5,%6,%7}, {%8,%9}, {%0,%1,%2,%3};" \
                 : "+f"(c0), "+f"(c1), "+f"(c2), "+f"(c3) \
                 : "r"(a0), "r"(a1), "r"(a2), "r"(a3), "r"(b0), "r"(b1))

// ============================================================================
// prep: fp32 -> fp16 convert (8 floats/thread, streaming loads) + bias-init
// of tail-tile output region
// ============================================================================
#define NX8 ((M_TOTAL * DIM) / 8)    // 2,097,152
#define NW8 ((DIM * DIM) / 8)        //   524,288
#define NT4 (TAIL_TILES * (BM * BN) / 4)     // 557,056
#define PREP_BLOCKS ((NX8 + NW8 + NT4) / 256)

__device__ __forceinline__ uint4 pack8(float4 v0, float4 v1) {
    __half2 h0 = __floats2half2_rn(v0.x, v0.y);
    __half2 h1 = __floats2half2_rn(v0.z, v0.w);
    __half2 h2 = __floats2half2_rn(v1.x, v1.y);
    __half2 h3 = __floats2half2_rn(v1.z, v1.w);
    uint4 p;
    p.x = *reinterpret_cast<uint32_t*>(&h0);
    p.y = *reinterpret_cast<uint32_t*>(&h1);
    p.z = *reinterpret_cast<uint32_t*>(&h2);
    p.w = *reinterpret_cast<uint32_t*>(&h3);
    return p;
}

__global__ void __launch_bounds__(256) prep_kernel(const float4* __restrict__ x,
                                                   const float4* __restrict__ W,
                                                   const float4* __restrict__ bias4,
                                                   float4* __restrict__ out4) {
    int i = blockIdx.x * 256 + threadIdx.x;
    if (i < NX8 + NW8) {
        const float4* src;
        uint4* dst;
        int j;
        if (i < NX8) { src = x; dst = reinterpret_cast<uint4*>(g_Xh); j = i; }
        else         { src = W; dst = reinterpret_cast<uint4*>(g_Wh); j = i - NX8; }
        // single-use loads: evict-first streaming keeps L2 for the fp16
        // scratch the GEMM will re-read
        float4 v0 = __ldcs(&src[2 * j]);
        float4 v1 = __ldcs(&src[2 * j + 1]);
        dst[j] = pack8(v0, v1);
    } else {
        int j = i - (NX8 + NW8);
        int tile = FULL_TILES + (j >> 12);
        int e = j & 4095;
        int r  = e >> 5;
        int c4 = e & 31;
        int m_tile = tile >> 4;
        int n_tile = tile & 15;
        int bidx = n_tile * 32 + c4;
        out4[(size_t)(m_tile * BM + r) * (DIM / 4) + bidx] = __ldg(&bias4[bidx]);
    }
}

// ============================================================================
// GEMM: 128x128 CTA tile, 8 warps (2Mx4N), warp tile 64x32, 3-stage mbarrier
// pipeline, early empty-arrive, 2 CTAs/SM. Tail tiles: half-K + RED.
// (Byte-identical to R11 — the proven 148.8us configuration.)
// ============================================================================
struct Frag { uint32_t a[4][4]; uint32_t b[2][4]; };

__device__ __forceinline__ void ldsm_frags(Frag& f, uint32_t aB, uint32_t bB,
                                           uint32_t a_base, uint32_t b_base, int k16) {
    const uint32_t kb = (uint32_t)(k16 * 32);
    #pragma unroll
    for (int mt = 0; mt < 4; mt++) {
        uint32_t off = swz(a_base + kb) + (uint32_t)(mt << 11);
        LDSM4(f.a[mt][0], f.a[mt][1], f.a[mt][2], f.a[mt][3], aB + off);
    }
    #pragma unroll
    for (int p = 0; p < 2; p++) {
        uint32_t off = swz(b_base + kb) + (uint32_t)(p << 11);
        LDSM4(f.b[p][0], f.b[p][1], f.b[p][2], f.b[p][3], bB + off);
    }
}

__device__ __forceinline__ void mma_frags(float c[4][4][4], const Frag& f) {
    #pragma unroll
    for (int mt = 0; mt < 4; mt++)
        #pragma unroll
        for (int nb = 0; nb < 4; nb++)
            MMA16816(c[mt][nb][0], c[mt][nb][1], c[mt][nb][2], c[mt][nb][3],
                     f.a[mt][0], f.a[mt][1], f.a[mt][2], f.a[mt][3],
                     f.b[nb >> 1][(nb & 1) * 2], f.b[nb >> 1][(nb & 1) * 2 + 1]);
}

__global__ void __launch_bounds__(THREADS, 2) gemm_fp16_kernel(
    float* __restrict__ out, const float* __restrict__ bias)
{
    extern __shared__ __align__(1024) char smem[];
    const uint32_t sbase = smem_u32(smem);
    const int tid  = threadIdx.x;
    const int lane = tid & 31;
    const int wid  = tid >> 5;
    const int warp_m = wid & 1;
    const int warp_n = wid >> 1;
    const int bid  = blockIdx.x;

    // tile / K-range assignment (tail split-K)
    int tile, kBase, iters;
    bool splitk;
    if (bid < FULL_TILES) {
        tile = bid;  kBase = 0;  iters = KITERS;  splitk = false;
    } else {
        int idx = bid - FULL_TILES;
        tile = FULL_TILES + (idx >> 1);
        kBase = (idx & 1) * (DIM / 2);
        iters = KITERS / 2;
        splitk = true;
    }
    const int mBase = (tile >> 4) * BM;
    const int nBase = (tile & 15) * BN;

    const uint32_t fullb  = sbase + TILES_BYTES;
    const uint32_t emptyb = sbase + TILES_BYTES + 24;

    if (tid == 0) {
        #pragma unroll
        for (int s = 0; s < STAGES; s++) {
            mbar_init(fullb  + s * 8, THREADS);
            mbar_init(emptyb + s * 8, 8);
        }
        #pragma unroll
        for (int k = 0; k < 8; k++) mbar_arrive(emptyb + 2 * 8);
    }

    const int n0 = nBase + warp_n * 32 + (lane & 3) * 2;
    float2 bb[4];
    #pragma unroll
    for (int nb = 0; nb < 4; nb++)
        bb[nb] = __ldg(reinterpret_cast<const float2*>(bias + n0 + nb * 8));

    const int ldr = tid >> 3;
    const int ldc = (tid & 7) * 8;
    const __half* aSrc = g_Xh + (size_t)(mBase + ldr) * DIM + kBase + ldc;
    const __half* bSrc = g_Wh + (size_t)(nBase + ldr) * DIM + kBase + ldc;
    const uint32_t dOff = swz((uint32_t)(ldr * 128 + ldc * 2));

    float c[4][4][4];
    #pragma unroll
    for (int mt = 0; mt < 4; mt++)
        #pragma unroll
        for (int nb = 0; nb < 4; nb++)
            #pragma unroll
            for (int r = 0; r < 4; r++) c[mt][nb][r] = 0.0f;

    __syncthreads();

    // prologue: produce chunks 0,1
    #pragma unroll
    for (int s = 0; s < 2; s++) {
        const uint32_t st = sbase + (uint32_t)s * STAGE_BYTES;
        #pragma unroll
        for (int i = 0; i < 4; i++)
            cp16(st + dOff + (uint32_t)(i << 12), aSrc + (size_t)(i * 32) * DIM + s * BK);
        #pragma unroll
        for (int i = 0; i < 4; i++)
            cp16(st + A_BYTES + dOff + (uint32_t)(i << 12), bSrc + (size_t)(i * 32) * DIM + s * BK);
        cp_arrive(fullb + s * 8);
    }

    const uint32_t a_base = (uint32_t)(((warp_m * 64 + (lane & 15)) << 7) + ((lane >> 4) << 4));
    const uint32_t b_base = (uint32_t)(((warp_n * 32 + ((lane >> 4) << 3) + (lane & 7)) << 7)
                                       + (((lane >> 3) & 1) << 4));

    uint32_t pf = 0, pe = 0;
    int s = 0;
    Frag f0, f1;

    for (int it = 0; it < iters; ++it) {
        // ---- consume chunk it from buffer s ----
        mbar_wait(fullb + s * 8, (pf >> s) & 1u);
        pf ^= (1u << s);

        const uint32_t aB = sbase + (uint32_t)s * STAGE_BYTES;
        const uint32_t bB = aB + A_BYTES;

        ldsm_frags(f0, aB, bB, a_base, b_base, 0);
        ldsm_frags(f1, aB, bB, a_base, b_base, 1);
        mma_frags(c, f0);

        // ---- produce chunk it+2 into buffer sw ----
        if (it + 2 < iters) {
            int sw = s + 2; if (sw >= STAGES) sw -= STAGES;
            mbar_wait(emptyb + sw * 8, (pe >> sw) & 1u);
            pe ^= (1u << sw);

            const uint32_t st = sbase + (uint32_t)sw * STAGE_BYTES;
            const int kc = (it + 2) * BK;
            #pragma unroll
            for (int i = 0; i < 4; i++)
                cp16(st + dOff + (uint32_t)(i << 12), aSrc + (size_t)(i * 32) * DIM + kc);
            #pragma unroll
            for (int i = 0; i < 4; i++)
                cp16(st + A_BYTES + dOff + (uint32_t)(i << 12), bSrc + (size_t)(i * 32) * DIM + kc);
            cp_arrive(fullb + sw * 8);
        }

        ldsm_frags(f0, aB, bB, a_base, b_base, 2);
        mma_frags(c, f1);
        ldsm_frags(f1, aB, bB, a_base, b_base, 3);

        // ALL smem reads of buffer s issued -> free buffer before tail MMAs
        if (lane == 0) mbar_arrive(emptyb + s * 8);

        mma_frags(c, f0);
        mma_frags(c, f1);

        s++; if (s == STAGES) s = 0;
    }

    // epilogue
    const int m0 = mBase + warp_m * 64 + (lane >> 2);
    if (!splitk) {
        #pragma unroll
        for (int mt = 0; mt < 4; mt++) {
            #pragma unroll
            for (int nb = 0; nb < 4; nb++) {
                const int row = m0 + mt * 16;
                const int col = n0 + nb * 8;
                float2 v0, v1;
                v0.x = c[mt][nb][0] + bb[nb].x;  v0.y = c[mt][nb][1] + bb[nb].y;
                v1.x = c[mt][nb][2] + bb[nb].x;  v1.y = c[mt][nb][3] + bb[nb].y;
                *reinterpret_cast<float2*>(out + (size_t)row * DIM + col) = v0;
                *reinterpret_cast<float2*>(out + (size_t)(row + 8) * DIM + col) = v1;
            }
        }
    } else {
        #pragma unroll
        for (int mt = 0; mt < 4; mt++) {
            #pragma unroll
            for (int nb = 0; nb < 4; nb++) {
                const int row = m0 + mt * 16;
                const int col = n0 + nb * 8;
                float* p0 = out + (size_t)row * DIM + col;
                float* p1 = out + (size_t)(row + 8) * DIM + col;
                redf(p0,     c[mt][nb][0]);
                redf(p0 + 1, c[mt][nb][1]);
                redf(p1,     c[mt][nb][2]);
                redf(p1 + 1, c[mt][nb][3]);
            }
        }
    }
}

// ============================================================================
// kernel_launch — graph-capturable, allocation-free
// ============================================================================
extern "C" void kernel_launch(void* const* d_in, const int* in_sizes, int n_in,
                              void* d_out, int out_size) {
    const float* x = (const float*)d_in[0];
    const float* W = (const float*)d_in[1];
    const float* b = (const float*)d_in[2];
    float* out = (float*)d_out;
    (void)in_sizes; (void)n_in; (void)out_size;

    prep_kernel<<<PREP_BLOCKS, 256>>>((const float4*)x, (const float4*)W,
                                      (const float4*)b, (float4*)out);

    cudaFuncSetAttribute(gemm_fp16_kernel,
                         cudaFuncAttributeMaxDynamicSharedMemorySize, SMEM_BYTES);
    gemm_fp16_kernel<<<GRID_TOTAL, THREADS, SMEM_BYTES>>>(out, b);
}

// round 14
// speedup vs baseline: 1.4781x; 1.0015x over previous
#include <cuda_runtime.h>
#include <cuda_fp16.h>
#include <cstdint>

// ============================================================================
// out[8192,2048] = x[8192,2048] @ W[2048,2048]^T + b   (fp32 in/out)
//
// fp16 mma.sync.m16n8k16, fp32 accum (tcgen05.ld rejected by plain sm_103
// ptxas). rel_err 2.06e-4 vs 1e-3 threshold.
//
// R14 = R13 (best: 168.7us = GEMM 150.1 + prep 18.6 @ HBM roofline)
//       + streaming epilogue stores (st.global.cs): output is never
//         re-read; evict-first keeps fp16 x/W scratch resident in L2 for
//         the producers (x rows re-read by 16 CTAs; Wh=8MB wants residency).
// Frozen by evidence: mainloop schedule (R10/R12 regressions; ~6KB L0 I$
// wall), tile config (regfile-capped), mbarrier protocol (R7 win),
// tail split-K (R9), prep (__ldcs, at roofline).
// ============================================================================

#define DIM      2048
#define M_TOTAL  8192
#define BM       128
#define BN       128
#define BK       64
#define THREADS  256
#define STAGES   3
#define KITERS   (DIM / BK)          // 32

#define NTILE_X  (DIM / BN)          // 16
#define NTILES   ((M_TOTAL / BM) * NTILE_X)   // 1024
#define FULL_TILES 888
#define TAIL_TILES (NTILES - FULL_TILES)      // 136
#define GRID_TOTAL (FULL_TILES + 2 * TAIL_TILES)  // 1160

__device__ __half g_Xh[(size_t)M_TOTAL * DIM];   // 32 MB
__device__ __half g_Wh[(size_t)DIM * DIM];       //  8 MB

#define A_BYTES     16384
#define STAGE_BYTES 32768
#define TILES_BYTES (STAGES * STAGE_BYTES)       // 98304
#define SMEM_BYTES  (TILES_BYTES + 64)

// ---------------------------------------------------------------------------
__device__ __forceinline__ uint32_t smem_u32(const void* p) {
    uint32_t a;
    asm("{ .reg .u64 t; cvta.to.shared.u64 t, %1; cvt.u32.u64 %0, t; }"
        : "=r"(a) : "l"(p));
    return a;
}
__device__ __forceinline__ uint32_t swz(uint32_t b) {   // SW128
    return b ^ ((b >> 3) & 0x70);
}
__device__ __forceinline__ void cp16(uint32_t dst, const void* src) {
    asm volatile("cp.async.cg.shared.global [%0], [%1], 16;"
                 :: "r"(dst), "l"(src));
}
__device__ __forceinline__ void cp_arrive(uint32_t mbar) {
    asm volatile("cp.async.mbarrier.arrive.noinc.shared::cta.b64 [%0];"
                 :: "r"(mbar) : "memory");
}
__device__ __forceinline__ void mbar_init(uint32_t mbar, uint32_t cnt) {
    asm volatile("mbarrier.init.shared.b64 [%0], %1;" :: "r"(mbar), "r"(cnt) : "memory");
}
__device__ __forceinline__ void mbar_arrive(uint32_t mbar) {
    asm volatile("mbarrier.arrive.shared::cta.b64 _, [%0];" :: "r"(mbar) : "memory");
}
__device__ __forceinline__ void mbar_wait(uint32_t mbar, uint32_t parity) {
    asm volatile(
        "{\n\t.reg .pred P;\n\t"
        "WAITLP_%=:\n\t"
        "mbarrier.try_wait.parity.acquire.cta.shared::cta.b64 P, [%0], %1, 0x989680;\n\t"
        "@!P bra WAITLP_%=;\n\t}"
        :: "r"(mbar), "r"(parity) : "memory");
}
__device__ __forceinline__ void redf(float* p, float v) {
    asm volatile("red.global.add.f32 [%0], %1;" :: "l"(p), "f"(v) : "memory");
}
// streaming (evict-first) 8-byte store: output is write-once
__device__ __forceinline__ void stcs2(float* p, float2 v) {
    asm volatile("st.global.cs.v2.f32 [%0], {%1, %2};"
                 :: "l"(p), "f"(v.x), "f"(v.y) : "memory");
}

#define LDSM4(r0, r1, r2, r3, addr) \
    asm volatile("ldmatrix.sync.aligned.m8n8.x4.shared.b16 {%0,%1,%2,%3}, [%4];" \
                 : "=r"(r0), "=r"(r1), "=r"(r2), "=r"(r3) : "r"(addr))

#define MMA16816(c0, c1, c2, c3, a0, a1, a2, a3, b0, b1) \
    asm volatile("mma.sync.aligned.m16n8k16.row.col.f32.f16.f16.f32 " \
                 "{%0,%1,%2,%3}, {%4,%5,%6,%7}, {%8,%9}, {%0,%1,%2,%3};" \
                 : "+f"(c0), "+f"(c1), "+f"(c2), "+f"(c3) \
                 : "r"(a0), "r"(a1), "r"(a2), "r"(a3), "r"(b0), "r"(b1))

// ============================================================================
// prep: fp32 -> fp16 convert (8 floats/thread, streaming loads) + bias-init
// of tail-tile output region
// ============================================================================
#define NX8 ((M_TOTAL * DIM) / 8)    // 2,097,152
#define NW8 ((DIM * DIM) / 8)        //   524,288
#define NT4 (TAIL_TILES * (BM * BN) / 4)     // 557,056
#define PREP_BLOCKS ((NX8 + NW8 + NT4) / 256)

__device__ __forceinline__ uint4 pack8(float4 v0, float4 v1) {
    __half2 h0 = __floats2half2_rn(v0.x, v0.y);
    __half2 h1 = __floats2half2_rn(v0.z, v0.w);
    __half2 h2 = __floats2half2_rn(v1.x, v1.y);
    __half2 h3 = __floats2half2_rn(v1.z, v1.w);
    uint4 p;
    p.x = *reinterpret_cast<uint32_t*>(&h0);
    p.y = *reinterpret_cast<uint32_t*>(&h1);
    p.z = *reinterpret_cast<uint32_t*>(&h2);
    p.w = *reinterpret_cast<uint32_t*>(&h3);
    return p;
}

__global__ void __launch_bounds__(256) prep_kernel(const float4* __restrict__ x,
                                                   const float4* __restrict__ W,
                                                   const float4* __restrict__ bias4,
                                                   float4* __restrict__ out4) {
    int i = blockIdx.x * 256 + threadIdx.x;
    if (i < NX8 + NW8) {
        const float4* src;
        uint4* dst;
        int j;
        if (i < NX8) { src = x; dst = reinterpret_cast<uint4*>(g_Xh); j = i; }
        else         { src = W; dst = reinterpret_cast<uint4*>(g_Wh); j = i - NX8; }
        float4 v0 = __ldcs(&src[2 * j]);
        float4 v1 = __ldcs(&src[2 * j + 1]);
        dst[j] = pack8(v0, v1);
    } else {
        int j = i - (NX8 + NW8);
        int tile = FULL_TILES + (j >> 12);
        int e = j & 4095;
        int r  = e >> 5;
        int c4 = e & 31;
        int m_tile = tile >> 4;
        int n_tile = tile & 15;
        int bidx = n_tile * 32 + c4;
        out4[(size_t)(m_tile * BM + r) * (DIM / 4) + bidx] = __ldg(&bias4[bidx]);
    }
}

// ============================================================================
// GEMM: 128x128 CTA tile, 8 warps (2Mx4N), warp tile 64x32, 3-stage mbarrier
// pipeline, early empty-arrive, 2 CTAs/SM. Tail tiles: half-K + RED.
// Mainloop byte-identical to R11/R13 (proven optimum).
// ============================================================================
struct Frag { uint32_t a[4][4]; uint32_t b[2][4]; };

__device__ __forceinline__ void ldsm_frags(Frag& f, uint32_t aB, uint32_t bB,
                                           uint32_t a_base, uint32_t b_base, int k16) {
    const uint32_t kb = (uint32_t)(k16 * 32);
    #pragma unroll
    for (int mt = 0; mt < 4; mt++) {
        uint32_t off = swz(a_base + kb) + (uint32_t)(mt << 11);
        LDSM4(f.a[mt][0], f.a[mt][1], f.a[mt][2], f.a[mt][3], aB + off);
    }
    #pragma unroll
    for (int p = 0; p < 2; p++) {
        uint32_t off = swz(b_base + kb) + (uint32_t)(p << 11);
        LDSM4(f.b[p][0], f.b[p][1], f.b[p][2], f.b[p][3], bB + off);
    }
}

__device__ __forceinline__ void mma_frags(float c[4][4][4], const Frag& f) {
    #pragma unroll
    for (int mt = 0; mt < 4; mt++)
        #pragma unroll
        for (int nb = 0; nb < 4; nb++)
            MMA16816(c[mt][nb][0], c[mt][nb][1], c[mt][nb][2], c[mt][nb][3],
                     f.a[mt][0], f.a[mt][1], f.a[mt][2], f.a[mt][3],
                     f.b[nb >> 1][(nb & 1) * 2], f.b[nb >> 1][(nb & 1) * 2 + 1]);
}

__global__ void __launch_bounds__(THREADS, 2) gemm_fp16_kernel(
    float* __restrict__ out, const float* __restrict__ bias)
{
    extern __shared__ __align__(1024) char smem[];
    const uint32_t sbase = smem_u32(smem);
    const int tid  = threadIdx.x;
    const int lane = tid & 31;
    const int wid  = tid >> 5;
    const int warp_m = wid & 1;
    const int warp_n = wid >> 1;
    const int bid  = blockIdx.x;

    // tile / K-range assignment (tail split-K)
    int tile, kBase, iters;
    bool splitk;
    if (bid < FULL_TILES) {
        tile = bid;  kBase = 0;  iters = KITERS;  splitk = false;
    } else {
        int idx = bid - FULL_TILES;
        tile = FULL_TILES + (idx >> 1);
        kBase = (idx & 1) * (DIM / 2);
        iters = KITERS / 2;
        splitk = true;
    }
    const int mBase = (tile >> 4) * BM;
    const int nBase = (tile & 15) * BN;

    const uint32_t fullb  = sbase + TILES_BYTES;
    const uint32_t emptyb = sbase + TILES_BYTES + 24;

    if (tid == 0) {
        #pragma unroll
        for (int s = 0; s < STAGES; s++) {
            mbar_init(fullb  + s * 8, THREADS);
            mbar_init(emptyb + s * 8, 8);
        }
        #pragma unroll
        for (int k = 0; k < 8; k++) mbar_arrive(emptyb + 2 * 8);
    }

    const int n0 = nBase + warp_n * 32 + (lane & 3) * 2;
    float2 bb[4];
    #pragma unroll
    for (int nb = 0; nb < 4; nb++)
        bb[nb] = __ldg(reinterpret_cast<const float2*>(bias + n0 + nb * 8));

    const int ldr = tid >> 3;
    const int ldc = (tid & 7) * 8;
    const __half* aSrc = g_Xh + (size_t)(mBase + ldr) * DIM + kBase + ldc;
    const __half* bSrc = g_Wh + (size_t)(nBase + ldr) * DIM + kBase + ldc;
    const uint32_t dOff = swz((uint32_t)(ldr * 128 + ldc * 2));

    float c[4][4][4];
    #pragma unroll
    for (int mt = 0; mt < 4; mt++)
        #pragma unroll
        for (int nb = 0; nb < 4; nb++)
            #pragma unroll
            for (int r = 0; r < 4; r++) c[mt][nb][r] = 0.0f;

    __syncthreads();

    // prologue: produce chunks 0,1
    #pragma unroll
    for (int s = 0; s < 2; s++) {
        const uint32_t st = sbase + (uint32_t)s * STAGE_BYTES;
        #pragma unroll
        for (int i = 0; i < 4; i++)
            cp16(st + dOff + (uint32_t)(i << 12), aSrc + (size_t)(i * 32) * DIM + s * BK);
        #pragma unroll
        for (int i = 0; i < 4; i++)
            cp16(st + A_BYTES + dOff + (uint32_t)(i << 12), bSrc + (size_t)(i * 32) * DIM + s * BK);
        cp_arrive(fullb + s * 8);
    }

    const uint32_t a_base = (uint32_t)(((warp_m * 64 + (lane & 15)) << 7) + ((lane >> 4) << 4));
    const uint32_t b_base = (uint32_t)(((warp_n * 32 + ((lane >> 4) << 3) + (lane & 7)) << 7)
                                       + (((lane >> 3) & 1) << 4));

    uint32_t pf = 0, pe = 0;
    int s = 0;
    Frag f0, f1;

    for (int it = 0; it < iters; ++it) {
        // ---- consume chunk it from buffer s ----
        mbar_wait(fullb + s * 8, (pf >> s) & 1u);
        pf ^= (1u << s);

        const uint32_t aB = sbase + (uint32_t)s * STAGE_BYTES;
        const uint32_t bB = aB + A_BYTES;

        ldsm_frags(f0, aB, bB, a_base, b_base, 0);
        ldsm_frags(f1, aB, bB, a_base, b_base, 1);
        mma_frags(c, f0);

        // ---- produce chunk it+2 into buffer sw ----
        if (it + 2 < iters) {
            int sw = s + 2; if (sw >= STAGES) sw -= STAGES;
            mbar_wait(emptyb + sw * 8, (pe >> sw) & 1u);
            pe ^= (1u << sw);

            const uint32_t st = sbase + (uint32_t)sw * STAGE_BYTES;
            const int kc = (it + 2) * BK;
            #pragma unroll
            for (int i = 0; i < 4; i++)
                cp16(st + dOff + (uint32_t)(i << 12), aSrc + (size_t)(i * 32) * DIM + kc);
            #pragma unroll
            for (int i = 0; i < 4; i++)
                cp16(st + A_BYTES + dOff + (uint32_t)(i << 12), bSrc + (size_t)(i * 32) * DIM + kc);
            cp_arrive(fullb + sw * 8);
        }

        ldsm_frags(f0, aB, bB, a_base, b_base, 2);
        mma_frags(c, f1);
        ldsm_frags(f1, aB, bB, a_base, b_base, 3);

        // ALL smem reads of buffer s issued -> free buffer before tail MMAs
        if (lane == 0) mbar_arrive(emptyb + s * 8);

        mma_frags(c, f0);
        mma_frags(c, f1);

        s++; if (s == STAGES) s = 0;
    }

    // epilogue: streaming stores (output never re-read; keep L2 for x/W)
    const int m0 = mBase + warp_m * 64 + (lane >> 2);
    if (!splitk) {
        #pragma unroll
        for (int mt = 0; mt < 4; mt++) {
            #pragma unroll
            for (int nb = 0; nb < 4; nb++) {
                const int row = m0 + mt * 16;
                const int col = n0 + nb * 8;
                float2 v0, v1;
                v0.x = c[mt][nb][0] + bb[nb].x;  v0.y = c[mt][nb][1] + bb[nb].y;
                v1.x = c[mt][nb][2] + bb[nb].x;  v1.y = c[mt][nb][3] + bb[nb].y;
                stcs2(out + (size_t)row * DIM + col, v0);
                stcs2(out + (size_t)(row + 8) * DIM + col, v1);
            }
        }
    } else {
        #pragma unroll
        for (int mt = 0; mt < 4; mt++) {
            #pragma unroll
            for (int nb = 0; nb < 4; nb++) {
                const int row = m0 + mt * 16;
                const int col = n0 + nb * 8;
                float* p0 = out + (size_t)row * DIM + col;
                float* p1 = out + (size_t)(row + 8) * DIM + col;
                redf(p0,     c[mt][nb][0]);
                redf(p0 + 1, c[mt][nb][1]);
                redf(p1,     c[mt][nb][2]);
                redf(p1 + 1, c[mt][nb][3]);
            }
        }
    }
}

// ============================================================================
// kernel_launch — graph-capturable, allocation-free
// ============================================================================
extern "C" void kernel_launch(void* const* d_in, const int* in_sizes, int n_in,
                              void* d_out, int out_size) {
    const float* x = (const float*)d_in[0];
    const float* W = (const float*)d_in[1];
    const float* b = (const float*)d_in[2];
    float* out = (float*)d_out;
    (void)in_sizes; (void)n_in; (void)out_size;

    prep_kernel<<<PREP_BLOCKS, 256>>>((const float4*)x, (const float4*)W,
                                      (const float4*)b, (float4*)out);

    cudaFuncSetAttribute(gemm_fp16_kernel,
                         cudaFuncAttributeMaxDynamicSharedMemorySize, SMEM_BYTES);
    gemm_fp16_kernel<<<GRID_TOTAL, THREADS, SMEM_BYTES>>>(out, b);
}